// round 10
// baseline (speedup 1.0000x reference)
#include <cuda_runtime.h>
#include <cstdint>

#define T_STEPS 256
#define BATCH   16
#define EMB     1024
#define HID     1024
#define VOCAB   32000
#define M_TOTAL (T_STEPS * BATCH)   // 4096

// Scratch (static device globals — allocation-free per harness rules)
__device__ float    g_U    [M_TOTAL * HID];   // 16 MB
__device__ float    g_Hs   [M_TOTAL * HID];   // 16 MB (fp32 hidden states)
__device__ float    g_Hs32 [M_TOTAL * HID];   // 16 MB (tf32-rounded copy)
__device__ float    g_Whq32[HID * VOCAB];     // 128 MB (tf32-rounded W_hq)
__device__ unsigned g_gen;                    // grid-barrier counter

// ===========================================================================
// helpers
// ===========================================================================
__device__ __forceinline__ float ftf32(float x) {
    unsigned u;
    asm("cvt.rna.tf32.f32 %0, %1;" : "=r"(u) : "f"(x));
    return __uint_as_float(u);
}
__device__ __forceinline__ uint32_t smem_u32(const void* p) {
    uint32_t a;
    asm("{ .reg .u64 t; cvta.to.shared.u64 t, %1; cvt.u32.u64 %0, t; }"
        : "=r"(a) : "l"(p));
    return a;
}
__device__ __forceinline__ void cp16(uint32_t dst, const void* src) {
    asm volatile("cp.async.cg.shared.global [%0], [%1], 16;"
                 :: "r"(dst), "l"(src) : "memory");
}
#define CP_COMMIT() asm volatile("cp.async.commit_group;" ::: "memory")
#define CP_WAIT2()  asm volatile("cp.async.wait_group 2;" ::: "memory")
#define CP_WAIT0()  asm volatile("cp.async.wait_group 0;" ::: "memory")

__device__ __forceinline__ void mma_tf32(float c[4], const unsigned a[4],
                                         const unsigned b[2]) {
    asm volatile(
        "mma.sync.aligned.m16n8k8.row.col.f32.tf32.tf32.f32 "
        "{%0,%1,%2,%3},{%4,%5,%6,%7},{%8,%9},{%0,%1,%2,%3};\n"
        : "+f"(c[0]), "+f"(c[1]), "+f"(c[2]), "+f"(c[3])
        : "r"(a[0]), "r"(a[1]), "r"(a[2]), "r"(a[3]), "r"(b[0]), "r"(b[1]));
}

// ===========================================================================
// K_round: elementwise tf32-rne rounding (float4 strided)
// ===========================================================================
__global__ void k_round(const float* __restrict__ src, float* __restrict__ dst,
                        int n4) {
    int i = blockIdx.x * blockDim.x + threadIdx.x;
    if (i < n4) {
        float4 v = ((const float4*)src)[i];
        v.x = ftf32(v.x); v.y = ftf32(v.y); v.z = ftf32(v.z); v.w = ftf32(v.w);
        ((float4*)dst)[i] = v;
    }
}

// ===========================================================================
// K1: U = gather(W_e, X) @ W_xh + b_h  via legacy mma.sync tf32
//     BM=BN=128, BK=32, 256 thr, 8 warps of 64x32
// ===========================================================================
#define AS_STRIDE 36
#define BS_STRIDE 132
#define AS_BUF (128 * AS_STRIDE)
#define BS_BUF (32 * BS_STRIDE)
#define K1_SMEM ((2 * AS_BUF + 2 * BS_BUF) * 4 + 512)

__global__ void k_embed_mma(const int* __restrict__ X,
                            const float* __restrict__ We,
                            const float* __restrict__ Wxh,
                            const float* __restrict__ bh) {
    extern __shared__ float sm[];
    float* As = sm;
    float* Bs = sm + 2 * AS_BUF;
    int*   sIdx = (int*)(sm + 2 * AS_BUF + 2 * BS_BUF);

    const int tid  = threadIdx.x;
    const int lane = tid & 31, warp = tid >> 5;
    const int gid  = lane >> 2, tig = lane & 3;
    const int wm = (warp >> 2) * 64;
    const int wn = (warp & 3) * 32;
    const int m0 = blockIdx.y * 128;
    const int n0 = blockIdx.x * 128;

    if (tid < 128) sIdx[tid] = X[m0 + tid];
    __syncthreads();

    float c[4][4][4];
    #pragma unroll
    for (int mi = 0; mi < 4; mi++)
        #pragma unroll
        for (int ni = 0; ni < 4; ni++)
            #pragma unroll
            for (int r = 0; r < 4; r++) c[mi][ni][r] = 0.f;

    float4 pa[4], pb[4];
    auto ldA = [&](int k0) {
        #pragma unroll
        for (int q = 0; q < 4; q++) {
            int id = tid + q * 256, r = id >> 3, c4 = id & 7;
            pa[q] = *(const float4*)&We[(size_t)sIdx[r] * EMB + k0 + c4 * 4];
        }
    };
    auto ldB = [&](int k0) {
        #pragma unroll
        for (int q = 0; q < 4; q++) {
            int id = tid + q * 256, r = id >> 5, c4 = id & 31;
            pb[q] = *(const float4*)&Wxh[(size_t)(k0 + r) * HID + n0 + c4 * 4];
        }
    };
    auto stA = [&](float* Ab) {
        #pragma unroll
        for (int q = 0; q < 4; q++) {
            int id = tid + q * 256, r = id >> 3, c4 = id & 7;
            float4 v = pa[q];
            v.x = ftf32(v.x); v.y = ftf32(v.y); v.z = ftf32(v.z); v.w = ftf32(v.w);
            *(float4*)&Ab[r * AS_STRIDE + c4 * 4] = v;
        }
    };
    auto stB = [&](float* Bb) {
        #pragma unroll
        for (int q = 0; q < 4; q++) {
            int id = tid + q * 256, r = id >> 5, c4 = id & 31;
            float4 v = pb[q];
            v.x = ftf32(v.x); v.y = ftf32(v.y); v.z = ftf32(v.z); v.w = ftf32(v.w);
            *(float4*)&Bb[r * BS_STRIDE + c4 * 4] = v;
        }
    };

    ldA(0); ldB(0);
    stA(As); stB(Bs);
    __syncthreads();

    int buf = 0;
    for (int kt = 0; kt < 32; kt++) {
        if (kt < 31) { ldA((kt + 1) * 32); ldB((kt + 1) * 32); }
        const float* Ab = As + buf * AS_BUF;
        const float* Bb = Bs + buf * BS_BUF;
        #pragma unroll
        for (int kk = 0; kk < 32; kk += 8) {
            unsigned af[4][4], bf[4][2];
            #pragma unroll
            for (int mi = 0; mi < 4; mi++) {
                int mr = wm + mi * 16 + gid;
                af[mi][0] = __float_as_uint(Ab[mr * AS_STRIDE + kk + tig]);
                af[mi][1] = __float_as_uint(Ab[(mr + 8) * AS_STRIDE + kk + tig]);
                af[mi][2] = __float_as_uint(Ab[mr * AS_STRIDE + kk + tig + 4]);
                af[mi][3] = __float_as_uint(Ab[(mr + 8) * AS_STRIDE + kk + tig + 4]);
            }
            #pragma unroll
            for (int ni = 0; ni < 4; ni++) {
                int nc = wn + ni * 8 + gid;
                bf[ni][0] = __float_as_uint(Bb[(kk + tig) * BS_STRIDE + nc]);
                bf[ni][1] = __float_as_uint(Bb[(kk + tig + 4) * BS_STRIDE + nc]);
            }
            #pragma unroll
            for (int mi = 0; mi < 4; mi++)
                #pragma unroll
                for (int ni = 0; ni < 4; ni++)
                    mma_tf32(c[mi][ni], af[mi], bf[ni]);
        }
        if (kt < 31) { stA(As + (buf ^ 1) * AS_BUF); stB(Bs + (buf ^ 1) * BS_BUF); }
        __syncthreads();
        buf ^= 1;
    }

    #pragma unroll
    for (int mi = 0; mi < 4; mi++) {
        int mr = m0 + wm + mi * 16 + gid;
        #pragma unroll
        for (int ni = 0; ni < 4; ni++) {
            int nc = n0 + wn + ni * 8 + tig * 2;
            float b0 = bh[nc], b1 = bh[nc + 1];
            float2 v0 = make_float2(c[mi][ni][0] + b0, c[mi][ni][1] + b1);
            float2 v1 = make_float2(c[mi][ni][2] + b0, c[mi][ni][3] + b1);
            *(float2*)&g_U[(size_t)mr * HID + nc]       = v0;
            *(float2*)&g_U[(size_t)(mr + 8) * HID + nc] = v1;
        }
    }
}

// ===========================================================================
// K2 (persistent): 256 recurrence steps, one launch (unchanged, known-good)
// ===========================================================================
#define NCTA 128
#define JPC  8
#define WS   1028
#define HS   260
#define CHUNK 256
#define RNN_SMEM ((JPC * WS + 2 * BATCH * HS + 256) * 4)

__global__ void __launch_bounds__(256, 1) k_rnn(const float* __restrict__ Whh) {
    extern __shared__ float sm[];
    float* Wsm = sm;
    float* hsm = sm + JPC * WS;
    float* red = hsm + 2 * BATCH * HS;

    const int tid  = threadIdx.x;
    const int pair = tid & 127;
    const int jl   = pair & 7;
    const int b    = pair >> 3;
    const int half = tid >> 7;
    const int j0   = blockIdx.x * JPC;
    const int koff = half * 128;

    for (int idx = tid; idx < JPC * HID; idx += 256) {
        int k = idx >> 3, jj = idx & 7;
        Wsm[jj * WS + k] = Whh[(size_t)k * HID + j0 + jj];
    }
    __syncthreads();

    for (int t = 0; t < T_STEPS; t++) {
        float hsum = 0.f;
        if (t > 0) {
            const float* hp = g_Hs + (size_t)(t - 1) * BATCH * HID;
            float4 acc = make_float4(0.f, 0.f, 0.f, 0.f);
            float4 r[4];
            #pragma unroll
            for (int q = 0; q < 4; q++) {
                int f4 = tid + q * 256, row = f4 >> 6, c4 = f4 & 63;
                r[q] = __ldcg((const float4*)&hp[(size_t)row * HID + c4 * 4]);
            }
            #pragma unroll
            for (int q = 0; q < 4; q++) {
                int f4 = tid + q * 256, row = f4 >> 6, c4 = f4 & 63;
                *(float4*)&hsm[row * HS + c4 * 4] = r[q];
            }
            __syncthreads();
            #pragma unroll
            for (int ch = 0; ch < 4; ch++) {
                if (ch < 3) {
                    #pragma unroll
                    for (int q = 0; q < 4; q++) {
                        int f4 = tid + q * 256, row = f4 >> 6, c4 = f4 & 63;
                        r[q] = __ldcg((const float4*)
                            &hp[(size_t)row * HID + (ch + 1) * CHUNK + c4 * 4]);
                    }
                }
                const float* wrow = Wsm + jl * WS + ch * CHUNK + koff;
                const float* hrow = hsm + (ch & 1) * BATCH * HS + b * HS + koff;
                #pragma unroll
                for (int kk = 0; kk < 128; kk += 4) {
                    float4 w4 = *(const float4*)&wrow[kk];
                    float4 h4 = *(const float4*)&hrow[kk];
                    acc.x += w4.x * h4.x;
                    acc.y += w4.y * h4.y;
                    acc.z += w4.z * h4.z;
                    acc.w += w4.w * h4.w;
                }
                if (ch < 3) {
                    float* dst = hsm + ((ch + 1) & 1) * BATCH * HS;
                    #pragma unroll
                    for (int q = 0; q < 4; q++) {
                        int f4 = tid + q * 256, row = f4 >> 6, c4 = f4 & 63;
                        *(float4*)&dst[row * HS + c4 * 4] = r[q];
                    }
                }
                __syncthreads();
            }
            hsum = (acc.x + acc.y) + (acc.z + acc.w);
        }

        red[tid] = hsum;
        __syncthreads();
        if (tid < 128) {
            const size_t m = (size_t)t * BATCH + b;
            float val = g_U[m * HID + j0 + jl] + red[tid] + red[tid + 128];
            g_Hs[m * HID + j0 + jl] = tanhf(val);
        }
        __threadfence();
        __syncthreads();

        if (t < T_STEPS - 1) {
            if (tid == 0) {
                atomicAdd(&g_gen, 1u);
                const unsigned target = (unsigned)NCTA * (t + 1);
                while (*(volatile unsigned*)&g_gen < target) __nanosleep(64);
                __threadfence();
            }
            __syncthreads();
        }
    }
}

// ===========================================================================
// K3: logits = Hs32 @ Whq32 + b_q   (legacy mma tf32, cp.async 4-stage)
//     CTA 128x256, BK=16, 256 thr, 8 warps of 64x64
//     A smem [m][k] stride 20, B smem [k][n] stride 264 (both conflict-free)
// ===========================================================================
#define BM3 128
#define BN3 256
#define BK3 16
#define A3S 20                              // A row stride (floats)
#define B3S 264                             // B row stride (floats)
#define A3_BYTES (BM3 * A3S * 4)            // 10240
#define B3_BYTES (BK3 * B3S * 4)            // 16896
#define STG3 (A3_BYTES + B3_BYTES)          // 27136
#define K3_SMEM (4 * STG3)                  // 108544

__global__ void __launch_bounds__(256, 1)
k_out_gemm2(const float* __restrict__ bq, float* __restrict__ out) {
    extern __shared__ char smc[];
    const uint32_t sb = smem_u32(smc);

    const int tid  = threadIdx.x;
    const int lane = tid & 31, warp = tid >> 5;
    const int gid  = lane >> 2, tig = lane & 3;
    const int wm = (warp & 1) * 64;       // 2 warps along M
    const int wn = (warp >> 1) * 64;      // 4 warps along N
    const int m0 = blockIdx.x * BM3;      // m fastest -> B tile L2 reuse
    const int n0 = blockIdx.y * BN3;

    auto issue = [&](int kt) {
        const int s = kt & 3;
        const uint32_t ab = sb + s * STG3;
        const uint32_t bb = ab + A3_BYTES;
        const int k0 = kt * BK3;
        #pragma unroll
        for (int q = 0; q < 2; q++) {                 // A: 512 16B chunks
            int id = tid + q * 256;
            int m = id >> 2, kq = id & 3;
            cp16(ab + m * (A3S * 4) + kq * 16,
                 &g_Hs32[(size_t)(m0 + m) * HID + k0 + kq * 4]);
        }
        #pragma unroll
        for (int q = 0; q < 4; q++) {                 // B: 1024 16B chunks
            int id = tid + q * 256;
            int k = id >> 6, n4 = id & 63;
            cp16(bb + k * (B3S * 4) + n4 * 16,
                 &g_Whq32[(size_t)(k0 + k) * VOCAB + n0 + n4 * 4]);
        }
        CP_COMMIT();
    };

    float c[4][8][4];
    #pragma unroll
    for (int mi = 0; mi < 4; mi++)
        #pragma unroll
        for (int ni = 0; ni < 8; ni++)
            #pragma unroll
            for (int r = 0; r < 4; r++) c[mi][ni][r] = 0.f;

    issue(0); issue(1); issue(2);

    for (int kt = 0; kt < 64; kt++) {
        CP_WAIT2();
        __syncthreads();
        if (kt + 3 < 64) issue(kt + 3);

        const int s = kt & 3;
        const float* As = (const float*)(smc + s * STG3);
        const float* Bs = (const float*)(smc + s * STG3 + A3_BYTES);

        #pragma unroll
        for (int kk = 0; kk < BK3; kk += 8) {
            unsigned af[4][4], bf[8][2];
            #pragma unroll
            for (int mi = 0; mi < 4; mi++) {
                int mr = wm + mi * 16 + gid;
                af[mi][0] = __float_as_uint(As[mr * A3S + kk + tig]);
                af[mi][1] = __float_as_uint(As[(mr + 8) * A3S + kk + tig]);
                af[mi][2] = __float_as_uint(As[mr * A3S + kk + tig + 4]);
                af[mi][3] = __float_as_uint(As[(mr + 8) * A3S + kk + tig + 4]);
            }
            #pragma unroll
            for (int ni = 0; ni < 8; ni++) {
                int nc = wn + ni * 8 + gid;
                bf[ni][0] = __float_as_uint(Bs[(kk + tig) * B3S + nc]);
                bf[ni][1] = __float_as_uint(Bs[(kk + tig + 4) * B3S + nc]);
            }
            #pragma unroll
            for (int mi = 0; mi < 4; mi++)
                #pragma unroll
                for (int ni = 0; ni < 8; ni++)
                    mma_tf32(c[mi][ni], af[mi], bf[ni]);
        }
        __syncthreads();
    }
    CP_WAIT0();

    // Epilogue: +bias, fp32 float2 stores
    #pragma unroll
    for (int mi = 0; mi < 4; mi++) {
        int mr = m0 + wm + mi * 16 + gid;
        #pragma unroll
        for (int ni = 0; ni < 8; ni++) {
            int nc = n0 + wn + ni * 8 + tig * 2;
            float b0 = bq[nc], b1 = bq[nc + 1];
            float2 v0 = make_float2(c[mi][ni][0] + b0, c[mi][ni][1] + b1);
            float2 v1 = make_float2(c[mi][ni][2] + b0, c[mi][ni][3] + b1);
            *(float2*)&out[(size_t)mr * VOCAB + nc]       = v0;
            *(float2*)&out[(size_t)(mr + 8) * VOCAB + nc] = v1;
        }
    }
}

// ===========================================================================
extern "C" void kernel_launch(void* const* d_in, const int* in_sizes, int n_in,
                              void* d_out, int out_size) {
    const int*   X   = (const int*)  d_in[0];
    const float* We  = (const float*)d_in[1];
    const float* Wxh = (const float*)d_in[2];
    const float* Whh = (const float*)d_in[3];
    const float* bh  = (const float*)d_in[4];
    const float* Whq = (const float*)d_in[5];
    const float* bq  = (const float*)d_in[6];
    float*       out = (float*)d_out;

    cudaFuncSetAttribute(k_embed_mma,
                         cudaFuncAttributeMaxDynamicSharedMemorySize, K1_SMEM);
    cudaFuncSetAttribute(k_rnn,
                         cudaFuncAttributeMaxDynamicSharedMemorySize, RNN_SMEM);
    cudaFuncSetAttribute(k_out_gemm2,
                         cudaFuncAttributeMaxDynamicSharedMemorySize, K3_SMEM);

    void *gen_ptr = nullptr, *whq32 = nullptr, *hs = nullptr, *hs32 = nullptr;
    cudaGetSymbolAddress(&gen_ptr, g_gen);
    cudaGetSymbolAddress(&whq32, g_Whq32);
    cudaGetSymbolAddress(&hs,    g_Hs);
    cudaGetSymbolAddress(&hs32,  g_Hs32);

    cudaMemsetAsync(gen_ptr, 0, sizeof(unsigned), 0);

    // Pre-round W_hq to tf32 (rne) once
    k_round<<<(HID * VOCAB / 4 + 255) / 256, 256>>>(Whq, (float*)whq32,
                                                    HID * VOCAB / 4);
    k_embed_mma<<<dim3(HID / 128, M_TOTAL / 128), 256, K1_SMEM>>>(X, We, Wxh, bh);
    k_rnn<<<NCTA, 256, RNN_SMEM>>>(Whh);
    // Round hidden states to tf32 (rne) for the output GEMM
    k_round<<<(M_TOTAL * HID / 4 + 255) / 256, 256>>>((const float*)hs,
                                                      (float*)hs32,
                                                      M_TOTAL * HID / 4);
    k_out_gemm2<<<dim3(M_TOTAL / BM3, VOCAB / BN3), 256, K3_SMEM>>>(bq, out);
}

// round 11
// speedup vs baseline: 1.2516x; 1.2516x over previous
#include <cuda_runtime.h>
#include <cstdint>

#define T_STEPS 256
#define BATCH   16
#define EMB     1024
#define HID     1024
#define VOCAB   32000
#define M_TOTAL (T_STEPS * BATCH)   // 4096

// Scratch (static device globals — allocation-free per harness rules)
__device__ float    g_U    [M_TOTAL * HID];   // 16 MB
__device__ float    g_Hs   [M_TOTAL * HID];   // 16 MB (fp32 hidden states)
__device__ float    g_Hs32 [M_TOTAL * HID];   // 16 MB (tf32-rounded copy)
__device__ float    g_Whq32[HID * VOCAB];     // 128 MB (tf32-rounded W_hq)
__device__ unsigned g_gen;                    // grid-barrier counter

// ===========================================================================
// helpers
// ===========================================================================
__device__ __forceinline__ float ftf32(float x) {
    unsigned u;
    asm("cvt.rna.tf32.f32 %0, %1;" : "=r"(u) : "f"(x));
    return __uint_as_float(u);
}
__device__ __forceinline__ unsigned ftf32u(float x) {
    unsigned u;
    asm("cvt.rna.tf32.f32 %0, %1;" : "=r"(u) : "f"(x));
    return u;
}
__device__ __forceinline__ uint32_t smem_u32(const void* p) {
    uint32_t a;
    asm("{ .reg .u64 t; cvta.to.shared.u64 t, %1; cvt.u32.u64 %0, t; }"
        : "=r"(a) : "l"(p));
    return a;
}
__device__ __forceinline__ void cp16(uint32_t dst, const void* src) {
    asm volatile("cp.async.cg.shared.global [%0], [%1], 16;"
                 :: "r"(dst), "l"(src) : "memory");
}
#define CP_COMMIT() asm volatile("cp.async.commit_group;" ::: "memory")
#define CP_WAIT2()  asm volatile("cp.async.wait_group 2;" ::: "memory")
#define CP_WAIT0()  asm volatile("cp.async.wait_group 0;" ::: "memory")

__device__ __forceinline__ void mma_tf32(float c[4], const unsigned a[4],
                                         const unsigned b[2]) {
    asm volatile(
        "mma.sync.aligned.m16n8k8.row.col.f32.tf32.tf32.f32 "
        "{%0,%1,%2,%3},{%4,%5,%6,%7},{%8,%9},{%0,%1,%2,%3};\n"
        : "+f"(c[0]), "+f"(c[1]), "+f"(c[2]), "+f"(c[3])
        : "r"(a[0]), "r"(a[1]), "r"(a[2]), "r"(a[3]), "r"(b[0]), "r"(b[1]));
}

// ===========================================================================
// K_round: elementwise tf32-rne rounding (float4 strided)
// ===========================================================================
__global__ void k_round(const float* __restrict__ src, float* __restrict__ dst,
                        int n4) {
    int i = blockIdx.x * blockDim.x + threadIdx.x;
    if (i < n4) {
        float4 v = ((const float4*)src)[i];
        v.x = ftf32(v.x); v.y = ftf32(v.y); v.z = ftf32(v.z); v.w = ftf32(v.w);
        ((float4*)dst)[i] = v;
    }
}

// ===========================================================================
// K1: U = gather(W_e, X) @ W_xh + b_h  via legacy mma.sync tf32
// ===========================================================================
#define AS_STRIDE 36
#define BS_STRIDE 132
#define AS_BUF (128 * AS_STRIDE)
#define BS_BUF (32 * BS_STRIDE)
#define K1_SMEM ((2 * AS_BUF + 2 * BS_BUF) * 4 + 512)

__global__ void k_embed_mma(const int* __restrict__ X,
                            const float* __restrict__ We,
                            const float* __restrict__ Wxh,
                            const float* __restrict__ bh) {
    extern __shared__ float sm[];
    float* As = sm;
    float* Bs = sm + 2 * AS_BUF;
    int*   sIdx = (int*)(sm + 2 * AS_BUF + 2 * BS_BUF);

    const int tid  = threadIdx.x;
    const int lane = tid & 31, warp = tid >> 5;
    const int gid  = lane >> 2, tig = lane & 3;
    const int wm = (warp >> 2) * 64;
    const int wn = (warp & 3) * 32;
    const int m0 = blockIdx.y * 128;
    const int n0 = blockIdx.x * 128;

    if (tid < 128) sIdx[tid] = X[m0 + tid];
    __syncthreads();

    float c[4][4][4];
    #pragma unroll
    for (int mi = 0; mi < 4; mi++)
        #pragma unroll
        for (int ni = 0; ni < 4; ni++)
            #pragma unroll
            for (int r = 0; r < 4; r++) c[mi][ni][r] = 0.f;

    float4 pa[4], pb[4];
    auto ldA = [&](int k0) {
        #pragma unroll
        for (int q = 0; q < 4; q++) {
            int id = tid + q * 256, r = id >> 3, c4 = id & 7;
            pa[q] = *(const float4*)&We[(size_t)sIdx[r] * EMB + k0 + c4 * 4];
        }
    };
    auto ldB = [&](int k0) {
        #pragma unroll
        for (int q = 0; q < 4; q++) {
            int id = tid + q * 256, r = id >> 5, c4 = id & 31;
            pb[q] = *(const float4*)&Wxh[(size_t)(k0 + r) * HID + n0 + c4 * 4];
        }
    };
    auto stA = [&](float* Ab) {
        #pragma unroll
        for (int q = 0; q < 4; q++) {
            int id = tid + q * 256, r = id >> 3, c4 = id & 7;
            float4 v = pa[q];
            v.x = ftf32(v.x); v.y = ftf32(v.y); v.z = ftf32(v.z); v.w = ftf32(v.w);
            *(float4*)&Ab[r * AS_STRIDE + c4 * 4] = v;
        }
    };
    auto stB = [&](float* Bb) {
        #pragma unroll
        for (int q = 0; q < 4; q++) {
            int id = tid + q * 256, r = id >> 5, c4 = id & 31;
            float4 v = pb[q];
            v.x = ftf32(v.x); v.y = ftf32(v.y); v.z = ftf32(v.z); v.w = ftf32(v.w);
            *(float4*)&Bb[r * BS_STRIDE + c4 * 4] = v;
        }
    };

    ldA(0); ldB(0);
    stA(As); stB(Bs);
    __syncthreads();

    int buf = 0;
    for (int kt = 0; kt < 32; kt++) {
        if (kt < 31) { ldA((kt + 1) * 32); ldB((kt + 1) * 32); }
        const float* Ab = As + buf * AS_BUF;
        const float* Bb = Bs + buf * BS_BUF;
        #pragma unroll
        for (int kk = 0; kk < 32; kk += 8) {
            unsigned af[4][4], bf[4][2];
            #pragma unroll
            for (int mi = 0; mi < 4; mi++) {
                int mr = wm + mi * 16 + gid;
                af[mi][0] = __float_as_uint(Ab[mr * AS_STRIDE + kk + tig]);
                af[mi][1] = __float_as_uint(Ab[(mr + 8) * AS_STRIDE + kk + tig]);
                af[mi][2] = __float_as_uint(Ab[mr * AS_STRIDE + kk + tig + 4]);
                af[mi][3] = __float_as_uint(Ab[(mr + 8) * AS_STRIDE + kk + tig + 4]);
            }
            #pragma unroll
            for (int ni = 0; ni < 4; ni++) {
                int nc = wn + ni * 8 + gid;
                bf[ni][0] = __float_as_uint(Bb[(kk + tig) * BS_STRIDE + nc]);
                bf[ni][1] = __float_as_uint(Bb[(kk + tig + 4) * BS_STRIDE + nc]);
            }
            #pragma unroll
            for (int mi = 0; mi < 4; mi++)
                #pragma unroll
                for (int ni = 0; ni < 4; ni++)
                    mma_tf32(c[mi][ni], af[mi], bf[ni]);
        }
        if (kt < 31) { stA(As + (buf ^ 1) * AS_BUF); stB(Bs + (buf ^ 1) * BS_BUF); }
        __syncthreads();
        buf ^= 1;
    }

    #pragma unroll
    for (int mi = 0; mi < 4; mi++) {
        int mr = m0 + wm + mi * 16 + gid;
        #pragma unroll
        for (int ni = 0; ni < 4; ni++) {
            int nc = n0 + wn + ni * 8 + tig * 2;
            float b0 = bh[nc], b1 = bh[nc + 1];
            float2 v0 = make_float2(c[mi][ni][0] + b0, c[mi][ni][1] + b1);
            float2 v1 = make_float2(c[mi][ni][2] + b0, c[mi][ni][3] + b1);
            *(float2*)&g_U[(size_t)mr * HID + nc]       = v0;
            *(float2*)&g_U[(size_t)(mr + 8) * HID + nc] = v1;
        }
    }
}

// ===========================================================================
// K2 (persistent, TENSOR-CORE): 256 recurrence steps, one launch.
//   64 CTAs x 512 threads (16 warps). CTA owns 16 output columns j.
//   Warp w owns k-slice [64w, 64w+64); W_hh B-fragments preloaded in
//   registers ONCE (32 regs). Per step: stage h_{t-1} in smem, 8 A-frags,
//   16 mma, smem reduce over 16 warps, +U, tanh, store, global barrier.
// ===========================================================================
#define NCTA2 64
#define JPC2  16
#define HSTR  1028   // h smem row stride (floats); 1028 % 32 == 4 -> conflict-free frags
#define RNN2_SMEM ((BATCH * HSTR + 16 * 256) * 4)   // 65792 + 16384 = 82176 B

__global__ void __launch_bounds__(512, 1) k_rnn_tc(const float* __restrict__ Whh) {
    extern __shared__ float sm[];
    float* hsm = sm;                    // [16][HSTR]
    float* red = sm + BATCH * HSTR;     // [16 warps][16 m][16 n]

    const int tid  = threadIdx.x;
    const int lane = tid & 31, warp = tid >> 5;   // 16 warps
    const int gid  = lane >> 2, tig = lane & 3;
    const int j0   = blockIdx.x * JPC2;
    const int kw   = warp * 64;

    // One-time: preload W_hh B-fragments (tf32) for this warp's k-slice.
    // bf[s][q]: n-subtile s (cols j0+8s..j0+8s+7), k-step q (k = kw+8q..+7)
    unsigned bf[2][8][2];
    #pragma unroll
    for (int s = 0; s < 2; s++)
        #pragma unroll
        for (int q = 0; q < 8; q++) {
            int k = kw + q * 8 + tig;
            int j = j0 + s * 8 + gid;
            bf[s][q][0] = ftf32u(Whh[(size_t)k * HID + j]);
            bf[s][q][1] = ftf32u(Whh[(size_t)(k + 4) * HID + j]);
        }

    for (int t = 0; t < T_STEPS; t++) {
        float c0[4] = {0.f, 0.f, 0.f, 0.f};
        float c1[4] = {0.f, 0.f, 0.f, 0.f};

        if (t > 0) {
            const float* hp = g_Hs + (size_t)(t - 1) * BATCH * HID;
            // stage h_{t-1}: 4096 float4 over 512 threads
            #pragma unroll
            for (int q = 0; q < 8; q++) {
                int f4 = tid + q * 512;
                int row = f4 >> 8, c4 = f4 & 255;
                float4 v = __ldcg((const float4*)&hp[(size_t)row * HID + c4 * 4]);
                *(float4*)&hsm[row * HSTR + c4 * 4] = v;
            }
            __syncthreads();

            #pragma unroll
            for (int q = 0; q < 8; q++) {
                const int k0 = kw + q * 8;
                unsigned af[4];
                af[0] = ftf32u(hsm[gid * HSTR + k0 + tig]);
                af[1] = ftf32u(hsm[(gid + 8) * HSTR + k0 + tig]);
                af[2] = ftf32u(hsm[gid * HSTR + k0 + tig + 4]);
                af[3] = ftf32u(hsm[(gid + 8) * HSTR + k0 + tig + 4]);
                mma_tf32(c0, af, bf[0][q]);
                mma_tf32(c1, af, bf[1][q]);
            }
        }

        // write per-warp partials: red[warp][m][n]
        {
            float* rw = red + warp * 256;
            rw[gid * 16 + tig * 2]           = c0[0];
            rw[gid * 16 + tig * 2 + 1]       = c0[1];
            rw[(gid + 8) * 16 + tig * 2]     = c0[2];
            rw[(gid + 8) * 16 + tig * 2 + 1] = c0[3];
            rw[gid * 16 + 8 + tig * 2]           = c1[0];
            rw[gid * 16 + 8 + tig * 2 + 1]       = c1[1];
            rw[(gid + 8) * 16 + 8 + tig * 2]     = c1[2];
            rw[(gid + 8) * 16 + 8 + tig * 2 + 1] = c1[3];
        }
        __syncthreads();

        if (tid < 256) {
            const int b = tid >> 4, n = tid & 15;
            float s = 0.f;
            if (t > 0) {
                #pragma unroll
                for (int w = 0; w < 16; w++)
                    s += red[w * 256 + b * 16 + n];
            }
            const size_t m = (size_t)t * BATCH + b;
            float val = g_U[m * HID + j0 + n] + s;
            g_Hs[m * HID + j0 + n] = tanhf(val);
        }
        __threadfence();
        __syncthreads();

        if (t < T_STEPS - 1) {
            if (tid == 0) {
                atomicAdd(&g_gen, 1u);
                const unsigned target = (unsigned)NCTA2 * (t + 1);
                while (*(volatile unsigned*)&g_gen < target) __nanosleep(32);
                __threadfence();
            }
            __syncthreads();
        }
    }
}

// ===========================================================================
// K3: logits = Hs32 @ Whq32 + b_q   (legacy mma tf32, cp.async 4-stage)
// ===========================================================================
#define BM3 128
#define BN3 256
#define BK3 16
#define A3S 20
#define B3S 264
#define A3_BYTES (BM3 * A3S * 4)
#define B3_BYTES (BK3 * B3S * 4)
#define STG3 (A3_BYTES + B3_BYTES)
#define K3_SMEM (4 * STG3)

__global__ void __launch_bounds__(256, 1)
k_out_gemm2(const float* __restrict__ bq, float* __restrict__ out) {
    extern __shared__ char smc[];
    const uint32_t sb = smem_u32(smc);

    const int tid  = threadIdx.x;
    const int lane = tid & 31, warp = tid >> 5;
    const int gid  = lane >> 2, tig = lane & 3;
    const int wm = (warp & 1) * 64;
    const int wn = (warp >> 1) * 64;
    const int m0 = blockIdx.x * BM3;
    const int n0 = blockIdx.y * BN3;

    auto issue = [&](int kt) {
        const int s = kt & 3;
        const uint32_t ab = sb + s * STG3;
        const uint32_t bb = ab + A3_BYTES;
        const int k0 = kt * BK3;
        #pragma unroll
        for (int q = 0; q < 2; q++) {
            int id = tid + q * 256;
            int m = id >> 2, kq = id & 3;
            cp16(ab + m * (A3S * 4) + kq * 16,
                 &g_Hs32[(size_t)(m0 + m) * HID + k0 + kq * 4]);
        }
        #pragma unroll
        for (int q = 0; q < 4; q++) {
            int id = tid + q * 256;
            int k = id >> 6, n4 = id & 63;
            cp16(bb + k * (B3S * 4) + n4 * 16,
                 &g_Whq32[(size_t)(k0 + k) * VOCAB + n0 + n4 * 4]);
        }
        CP_COMMIT();
    };

    float c[4][8][4];
    #pragma unroll
    for (int mi = 0; mi < 4; mi++)
        #pragma unroll
        for (int ni = 0; ni < 8; ni++)
            #pragma unroll
            for (int r = 0; r < 4; r++) c[mi][ni][r] = 0.f;

    issue(0); issue(1); issue(2);

    for (int kt = 0; kt < 64; kt++) {
        CP_WAIT2();
        __syncthreads();
        if (kt + 3 < 64) issue(kt + 3);

        const int s = kt & 3;
        const float* As = (const float*)(smc + s * STG3);
        const float* Bs = (const float*)(smc + s * STG3 + A3_BYTES);

        #pragma unroll
        for (int kk = 0; kk < BK3; kk += 8) {
            unsigned af[4][4], bf[8][2];
            #pragma unroll
            for (int mi = 0; mi < 4; mi++) {
                int mr = wm + mi * 16 + gid;
                af[mi][0] = __float_as_uint(As[mr * A3S + kk + tig]);
                af[mi][1] = __float_as_uint(As[(mr + 8) * A3S + kk + tig]);
                af[mi][2] = __float_as_uint(As[mr * A3S + kk + tig + 4]);
                af[mi][3] = __float_as_uint(As[(mr + 8) * A3S + kk + tig + 4]);
            }
            #pragma unroll
            for (int ni = 0; ni < 8; ni++) {
                int nc = wn + ni * 8 + gid;
                bf[ni][0] = __float_as_uint(Bs[(kk + tig) * B3S + nc]);
                bf[ni][1] = __float_as_uint(Bs[(kk + tig + 4) * B3S + nc]);
            }
            #pragma unroll
            for (int mi = 0; mi < 4; mi++)
                #pragma unroll
                for (int ni = 0; ni < 8; ni++)
                    mma_tf32(c[mi][ni], af[mi], bf[ni]);
        }
        __syncthreads();
    }
    CP_WAIT0();

    #pragma unroll
    for (int mi = 0; mi < 4; mi++) {
        int mr = m0 + wm + mi * 16 + gid;
        #pragma unroll
        for (int ni = 0; ni < 8; ni++) {
            int nc = n0 + wn + ni * 8 + tig * 2;
            float b0 = bq[nc], b1 = bq[nc + 1];
            float2 v0 = make_float2(c[mi][ni][0] + b0, c[mi][ni][1] + b1);
            float2 v1 = make_float2(c[mi][ni][2] + b0, c[mi][ni][3] + b1);
            *(float2*)&out[(size_t)mr * VOCAB + nc]       = v0;
            *(float2*)&out[(size_t)(mr + 8) * VOCAB + nc] = v1;
        }
    }
}

// ===========================================================================
extern "C" void kernel_launch(void* const* d_in, const int* in_sizes, int n_in,
                              void* d_out, int out_size) {
    const int*   X   = (const int*)  d_in[0];
    const float* We  = (const float*)d_in[1];
    const float* Wxh = (const float*)d_in[2];
    const float* Whh = (const float*)d_in[3];
    const float* bh  = (const float*)d_in[4];
    const float* Whq = (const float*)d_in[5];
    const float* bq  = (const float*)d_in[6];
    float*       out = (float*)d_out;

    cudaFuncSetAttribute(k_embed_mma,
                         cudaFuncAttributeMaxDynamicSharedMemorySize, K1_SMEM);
    cudaFuncSetAttribute(k_rnn_tc,
                         cudaFuncAttributeMaxDynamicSharedMemorySize, RNN2_SMEM);
    cudaFuncSetAttribute(k_out_gemm2,
                         cudaFuncAttributeMaxDynamicSharedMemorySize, K3_SMEM);

    void *gen_ptr = nullptr, *whq32 = nullptr, *hs = nullptr, *hs32 = nullptr;
    cudaGetSymbolAddress(&gen_ptr, g_gen);
    cudaGetSymbolAddress(&whq32, g_Whq32);
    cudaGetSymbolAddress(&hs,    g_Hs);
    cudaGetSymbolAddress(&hs32,  g_Hs32);

    cudaMemsetAsync(gen_ptr, 0, sizeof(unsigned), 0);

    k_round<<<(HID * VOCAB / 4 + 255) / 256, 256>>>(Whq, (float*)whq32,
                                                    HID * VOCAB / 4);
    k_embed_mma<<<dim3(HID / 128, M_TOTAL / 128), 256, K1_SMEM>>>(X, We, Wxh, bh);
    k_rnn_tc<<<NCTA2, 512, RNN2_SMEM>>>(Whh);
    k_round<<<(M_TOTAL * HID / 4 + 255) / 256, 256>>>((const float*)hs,
                                                      (float*)hs32,
                                                      M_TOTAL * HID / 4);
    k_out_gemm2<<<dim3(M_TOTAL / BM3, VOCAB / BN3), 256, K3_SMEM>>>(bq, out);
}

// round 12
// speedup vs baseline: 1.2715x; 1.0159x over previous
#include <cuda_runtime.h>
#include <cstdint>

#define T_STEPS 256
#define BATCH   16
#define EMB     1024
#define HID     1024
#define VOCAB   32000
#define M_TOTAL (T_STEPS * BATCH)   // 4096

// Scratch (static device globals — allocation-free per harness rules)
__device__ float    g_U    [M_TOTAL * HID];   // 16 MB
__device__ float    g_Hs   [M_TOTAL * HID];   // 16 MB (fp32 hidden states)
__device__ float    g_Hs32 [M_TOTAL * HID];   // 16 MB (tf32-rounded copy)
__device__ float    g_Whq32[HID * VOCAB];     // 128 MB (tf32-rounded W_hq)
__device__ unsigned g_gen;                    // grid-barrier counter

// ===========================================================================
// helpers
// ===========================================================================
__device__ __forceinline__ float ftf32(float x) {
    unsigned u;
    asm("cvt.rna.tf32.f32 %0, %1;" : "=r"(u) : "f"(x));
    return __uint_as_float(u);
}
__device__ __forceinline__ unsigned ftf32u(float x) {
    unsigned u;
    asm("cvt.rna.tf32.f32 %0, %1;" : "=r"(u) : "f"(x));
    return u;
}
__device__ __forceinline__ uint32_t smem_u32(const void* p) {
    uint32_t a;
    asm("{ .reg .u64 t; cvta.to.shared.u64 t, %1; cvt.u32.u64 %0, t; }"
        : "=r"(a) : "l"(p));
    return a;
}
__device__ __forceinline__ void cp16(uint32_t dst, const void* src) {
    asm volatile("cp.async.cg.shared.global [%0], [%1], 16;"
                 :: "r"(dst), "l"(src) : "memory");
}
#define CP_COMMIT() asm volatile("cp.async.commit_group;" ::: "memory")
#define CP_WAIT2()  asm volatile("cp.async.wait_group 2;" ::: "memory")
#define CP_WAIT0()  asm volatile("cp.async.wait_group 0;" ::: "memory")

__device__ __forceinline__ void mma_tf32(float c[4], const unsigned a[4],
                                         const unsigned b[2]) {
    asm volatile(
        "mma.sync.aligned.m16n8k8.row.col.f32.tf32.tf32.f32 "
        "{%0,%1,%2,%3},{%4,%5,%6,%7},{%8,%9},{%0,%1,%2,%3};\n"
        : "+f"(c[0]), "+f"(c[1]), "+f"(c[2]), "+f"(c[3])
        : "r"(a[0]), "r"(a[1]), "r"(a[2]), "r"(a[3]), "r"(b[0]), "r"(b[1]));
}

// ===========================================================================
// K_round: elementwise tf32-rne rounding, 4 float4 per thread (MLP=4)
// ===========================================================================
__global__ void k_round4(const float* __restrict__ src, float* __restrict__ dst,
                         int n4) {
    int base = blockIdx.x * blockDim.x * 4 + threadIdx.x;
    float4 v[4];
    #pragma unroll
    for (int q = 0; q < 4; q++) {
        int i = base + q * blockDim.x;
        if (i < n4) v[q] = ((const float4*)src)[i];
    }
    #pragma unroll
    for (int q = 0; q < 4; q++) {
        int i = base + q * blockDim.x;
        if (i < n4) {
            float4 t = v[q];
            t.x = ftf32(t.x); t.y = ftf32(t.y); t.z = ftf32(t.z); t.w = ftf32(t.w);
            ((float4*)dst)[i] = t;
        }
    }
}

// ===========================================================================
// K1: U = gather(W_e, X) @ W_xh + b_h  via legacy mma.sync tf32
// ===========================================================================
#define AS_STRIDE 36
#define BS_STRIDE 132
#define AS_BUF (128 * AS_STRIDE)
#define BS_BUF (32 * BS_STRIDE)
#define K1_SMEM ((2 * AS_BUF + 2 * BS_BUF) * 4 + 512)

__global__ void k_embed_mma(const int* __restrict__ X,
                            const float* __restrict__ We,
                            const float* __restrict__ Wxh,
                            const float* __restrict__ bh) {
    extern __shared__ float sm[];
    float* As = sm;
    float* Bs = sm + 2 * AS_BUF;
    int*   sIdx = (int*)(sm + 2 * AS_BUF + 2 * BS_BUF);

    const int tid  = threadIdx.x;
    const int lane = tid & 31, warp = tid >> 5;
    const int gid  = lane >> 2, tig = lane & 3;
    const int wm = (warp >> 2) * 64;
    const int wn = (warp & 3) * 32;
    const int m0 = blockIdx.y * 128;
    const int n0 = blockIdx.x * 128;

    if (tid < 128) sIdx[tid] = X[m0 + tid];
    __syncthreads();

    float c[4][4][4];
    #pragma unroll
    for (int mi = 0; mi < 4; mi++)
        #pragma unroll
        for (int ni = 0; ni < 4; ni++)
            #pragma unroll
            for (int r = 0; r < 4; r++) c[mi][ni][r] = 0.f;

    float4 pa[4], pb[4];
    auto ldA = [&](int k0) {
        #pragma unroll
        for (int q = 0; q < 4; q++) {
            int id = tid + q * 256, r = id >> 3, c4 = id & 7;
            pa[q] = *(const float4*)&We[(size_t)sIdx[r] * EMB + k0 + c4 * 4];
        }
    };
    auto ldB = [&](int k0) {
        #pragma unroll
        for (int q = 0; q < 4; q++) {
            int id = tid + q * 256, r = id >> 5, c4 = id & 31;
            pb[q] = *(const float4*)&Wxh[(size_t)(k0 + r) * HID + n0 + c4 * 4];
        }
    };
    auto stA = [&](float* Ab) {
        #pragma unroll
        for (int q = 0; q < 4; q++) {
            int id = tid + q * 256, r = id >> 3, c4 = id & 7;
            float4 v = pa[q];
            v.x = ftf32(v.x); v.y = ftf32(v.y); v.z = ftf32(v.z); v.w = ftf32(v.w);
            *(float4*)&Ab[r * AS_STRIDE + c4 * 4] = v;
        }
    };
    auto stB = [&](float* Bb) {
        #pragma unroll
        for (int q = 0; q < 4; q++) {
            int id = tid + q * 256, r = id >> 5, c4 = id & 31;
            float4 v = pb[q];
            v.x = ftf32(v.x); v.y = ftf32(v.y); v.z = ftf32(v.z); v.w = ftf32(v.w);
            *(float4*)&Bb[r * BS_STRIDE + c4 * 4] = v;
        }
    };

    ldA(0); ldB(0);
    stA(As); stB(Bs);
    __syncthreads();

    int buf = 0;
    for (int kt = 0; kt < 32; kt++) {
        if (kt < 31) { ldA((kt + 1) * 32); ldB((kt + 1) * 32); }
        const float* Ab = As + buf * AS_BUF;
        const float* Bb = Bs + buf * BS_BUF;
        #pragma unroll
        for (int kk = 0; kk < 32; kk += 8) {
            unsigned af[4][4], bf[4][2];
            #pragma unroll
            for (int mi = 0; mi < 4; mi++) {
                int mr = wm + mi * 16 + gid;
                af[mi][0] = __float_as_uint(Ab[mr * AS_STRIDE + kk + tig]);
                af[mi][1] = __float_as_uint(Ab[(mr + 8) * AS_STRIDE + kk + tig]);
                af[mi][2] = __float_as_uint(Ab[mr * AS_STRIDE + kk + tig + 4]);
                af[mi][3] = __float_as_uint(Ab[(mr + 8) * AS_STRIDE + kk + tig + 4]);
            }
            #pragma unroll
            for (int ni = 0; ni < 4; ni++) {
                int nc = wn + ni * 8 + gid;
                bf[ni][0] = __float_as_uint(Bb[(kk + tig) * BS_STRIDE + nc]);
                bf[ni][1] = __float_as_uint(Bb[(kk + tig + 4) * BS_STRIDE + nc]);
            }
            #pragma unroll
            for (int mi = 0; mi < 4; mi++)
                #pragma unroll
                for (int ni = 0; ni < 4; ni++)
                    mma_tf32(c[mi][ni], af[mi], bf[ni]);
        }
        if (kt < 31) { stA(As + (buf ^ 1) * AS_BUF); stB(Bs + (buf ^ 1) * BS_BUF); }
        __syncthreads();
        buf ^= 1;
    }

    #pragma unroll
    for (int mi = 0; mi < 4; mi++) {
        int mr = m0 + wm + mi * 16 + gid;
        #pragma unroll
        for (int ni = 0; ni < 4; ni++) {
            int nc = n0 + wn + ni * 8 + tig * 2;
            float b0 = bh[nc], b1 = bh[nc + 1];
            float2 v0 = make_float2(c[mi][ni][0] + b0, c[mi][ni][1] + b1);
            float2 v1 = make_float2(c[mi][ni][2] + b0, c[mi][ni][3] + b1);
            *(float2*)&g_U[(size_t)mr * HID + nc]       = v0;
            *(float2*)&g_U[(size_t)(mr + 8) * HID + nc] = v1;
        }
    }
}

// ===========================================================================
// K2 (persistent, tensor-core recurrence) — now also emits tf32-rounded h
// ===========================================================================
#define NCTA2 64
#define JPC2  16
#define HSTR  1028
#define RNN2_SMEM ((BATCH * HSTR + 16 * 256) * 4)

__global__ void __launch_bounds__(512, 1) k_rnn_tc(const float* __restrict__ Whh) {
    extern __shared__ float sm[];
    float* hsm = sm;
    float* red = sm + BATCH * HSTR;

    const int tid  = threadIdx.x;
    const int lane = tid & 31, warp = tid >> 5;
    const int gid  = lane >> 2, tig = lane & 3;
    const int j0   = blockIdx.x * JPC2;
    const int kw   = warp * 64;

    unsigned bf[2][8][2];
    #pragma unroll
    for (int s = 0; s < 2; s++)
        #pragma unroll
        for (int q = 0; q < 8; q++) {
            int k = kw + q * 8 + tig;
            int j = j0 + s * 8 + gid;
            bf[s][q][0] = ftf32u(Whh[(size_t)k * HID + j]);
            bf[s][q][1] = ftf32u(Whh[(size_t)(k + 4) * HID + j]);
        }

    for (int t = 0; t < T_STEPS; t++) {
        float c0[4] = {0.f, 0.f, 0.f, 0.f};
        float c1[4] = {0.f, 0.f, 0.f, 0.f};

        if (t > 0) {
            const float* hp = g_Hs + (size_t)(t - 1) * BATCH * HID;
            #pragma unroll
            for (int q = 0; q < 8; q++) {
                int f4 = tid + q * 512;
                int row = f4 >> 8, c4 = f4 & 255;
                float4 v = __ldcg((const float4*)&hp[(size_t)row * HID + c4 * 4]);
                *(float4*)&hsm[row * HSTR + c4 * 4] = v;
            }
            __syncthreads();

            #pragma unroll
            for (int q = 0; q < 8; q++) {
                const int k0 = kw + q * 8;
                unsigned af[4];
                af[0] = ftf32u(hsm[gid * HSTR + k0 + tig]);
                af[1] = ftf32u(hsm[(gid + 8) * HSTR + k0 + tig]);
                af[2] = ftf32u(hsm[gid * HSTR + k0 + tig + 4]);
                af[3] = ftf32u(hsm[(gid + 8) * HSTR + k0 + tig + 4]);
                mma_tf32(c0, af, bf[0][q]);
                mma_tf32(c1, af, bf[1][q]);
            }
        }

        {
            float* rw = red + warp * 256;
            rw[gid * 16 + tig * 2]           = c0[0];
            rw[gid * 16 + tig * 2 + 1]       = c0[1];
            rw[(gid + 8) * 16 + tig * 2]     = c0[2];
            rw[(gid + 8) * 16 + tig * 2 + 1] = c0[3];
            rw[gid * 16 + 8 + tig * 2]           = c1[0];
            rw[gid * 16 + 8 + tig * 2 + 1]       = c1[1];
            rw[(gid + 8) * 16 + 8 + tig * 2]     = c1[2];
            rw[(gid + 8) * 16 + 8 + tig * 2 + 1] = c1[3];
        }
        __syncthreads();

        if (tid < 256) {
            const int b = tid >> 4, n = tid & 15;
            float s = 0.f;
            if (t > 0) {
                #pragma unroll
                for (int w = 0; w < 16; w++)
                    s += red[w * 256 + b * 16 + n];
            }
            const size_t m = (size_t)t * BATCH + b;
            float val = tanhf(g_U[m * HID + j0 + n] + s);
            g_Hs[m * HID + j0 + n]   = val;
            g_Hs32[m * HID + j0 + n] = ftf32(val);   // fused tf32 copy for K3
        }
        __threadfence();
        __syncthreads();

        if (t < T_STEPS - 1) {
            if (tid == 0) {
                atomicAdd(&g_gen, 1u);
                const unsigned target = (unsigned)NCTA2 * (t + 1);
                while (*(volatile unsigned*)&g_gen < target) __nanosleep(32);
                __threadfence();
            }
            __syncthreads();
        }
    }
}

// ===========================================================================
// K3: logits = Hs32 @ Whq32 + b_q   (legacy mma tf32, cp.async 4-stage)
//     ONE __syncthreads per kt; fragment double-buffering across kk chunks
// ===========================================================================
#define BM3 128
#define BN3 256
#define BK3 16
#define A3S 20
#define B3S 264
#define A3_BYTES (BM3 * A3S * 4)
#define B3_BYTES (BK3 * B3S * 4)
#define STG3 (A3_BYTES + B3_BYTES)
#define K3_SMEM (4 * STG3)

__global__ void __launch_bounds__(256)
k_out_gemm2(const float* __restrict__ bq, float* __restrict__ out) {
    extern __shared__ char smc[];
    const uint32_t sb = smem_u32(smc);

    const int tid  = threadIdx.x;
    const int lane = tid & 31, warp = tid >> 5;
    const int gid  = lane >> 2, tig = lane & 3;
    const int wm = (warp & 1) * 64;
    const int wn = (warp >> 1) * 64;
    const int m0 = blockIdx.x * BM3;
    const int n0 = blockIdx.y * BN3;

    auto issue = [&](int kt) {
        const int s = kt & 3;
        const uint32_t ab = sb + s * STG3;
        const uint32_t bb = ab + A3_BYTES;
        const int k0 = kt * BK3;
        #pragma unroll
        for (int q = 0; q < 2; q++) {
            int id = tid + q * 256;
            int m = id >> 2, kq = id & 3;
            cp16(ab + m * (A3S * 4) + kq * 16,
                 &g_Hs32[(size_t)(m0 + m) * HID + k0 + kq * 4]);
        }
        #pragma unroll
        for (int q = 0; q < 4; q++) {
            int id = tid + q * 256;
            int k = id >> 6, n4 = id & 63;
            cp16(bb + k * (B3S * 4) + n4 * 16,
                 &g_Whq32[(size_t)(k0 + k) * VOCAB + n0 + n4 * 4]);
        }
        CP_COMMIT();
    };

    float c[4][8][4];
    #pragma unroll
    for (int mi = 0; mi < 4; mi++)
        #pragma unroll
        for (int ni = 0; ni < 8; ni++)
            #pragma unroll
            for (int r = 0; r < 4; r++) c[mi][ni][r] = 0.f;

    issue(0); issue(1); issue(2);

    unsigned af[2][4][4], bfr[2][8][2];

    auto ld_frags = [&](const float* As, const float* Bs, int kk, int reg) {
        #pragma unroll
        for (int mi = 0; mi < 4; mi++) {
            int mr = wm + mi * 16 + gid;
            af[reg][mi][0] = __float_as_uint(As[mr * A3S + kk + tig]);
            af[reg][mi][1] = __float_as_uint(As[(mr + 8) * A3S + kk + tig]);
            af[reg][mi][2] = __float_as_uint(As[mr * A3S + kk + tig + 4]);
            af[reg][mi][3] = __float_as_uint(As[(mr + 8) * A3S + kk + tig + 4]);
        }
        #pragma unroll
        for (int ni = 0; ni < 8; ni++) {
            int nc = wn + ni * 8 + gid;
            bfr[reg][ni][0] = __float_as_uint(Bs[(kk + tig) * B3S + nc]);
            bfr[reg][ni][1] = __float_as_uint(Bs[(kk + tig + 4) * B3S + nc]);
        }
    };
    auto do_mma = [&](int reg) {
        #pragma unroll
        for (int mi = 0; mi < 4; mi++)
            #pragma unroll
            for (int ni = 0; ni < 8; ni++)
                mma_tf32(c[mi][ni], af[reg][mi], bfr[reg][ni]);
    };

    for (int kt = 0; kt < 64; kt++) {
        CP_WAIT2();
        __syncthreads();           // stage kt ready; all readers of kt-1 done
        if (kt + 3 < 64) issue(kt + 3);

        const int s = kt & 3;
        const float* As = (const float*)(smc + s * STG3);
        const float* Bs = (const float*)(smc + s * STG3 + A3_BYTES);

        ld_frags(As, Bs, 0, 0);    // kk = 0
        ld_frags(As, Bs, 8, 1);    // kk = 8 (prefetched before first mma wave)
        do_mma(0);
        do_mma(1);
    }
    CP_WAIT0();

    #pragma unroll
    for (int mi = 0; mi < 4; mi++) {
        int mr = m0 + wm + mi * 16 + gid;
        #pragma unroll
        for (int ni = 0; ni < 8; ni++) {
            int nc = n0 + wn + ni * 8 + tig * 2;
            float b0 = bq[nc], b1 = bq[nc + 1];
            float2 v0 = make_float2(c[mi][ni][0] + b0, c[mi][ni][1] + b1);
            float2 v1 = make_float2(c[mi][ni][2] + b0, c[mi][ni][3] + b1);
            *(float2*)&out[(size_t)mr * VOCAB + nc]       = v0;
            *(float2*)&out[(size_t)(mr + 8) * VOCAB + nc] = v1;
        }
    }
}

// ===========================================================================
extern "C" void kernel_launch(void* const* d_in, const int* in_sizes, int n_in,
                              void* d_out, int out_size) {
    const int*   X   = (const int*)  d_in[0];
    const float* We  = (const float*)d_in[1];
    const float* Wxh = (const float*)d_in[2];
    const float* Whh = (const float*)d_in[3];
    const float* bh  = (const float*)d_in[4];
    const float* Whq = (const float*)d_in[5];
    const float* bq  = (const float*)d_in[6];
    float*       out = (float*)d_out;

    cudaFuncSetAttribute(k_embed_mma,
                         cudaFuncAttributeMaxDynamicSharedMemorySize, K1_SMEM);
    cudaFuncSetAttribute(k_rnn_tc,
                         cudaFuncAttributeMaxDynamicSharedMemorySize, RNN2_SMEM);
    cudaFuncSetAttribute(k_out_gemm2,
                         cudaFuncAttributeMaxDynamicSharedMemorySize, K3_SMEM);

    void *gen_ptr = nullptr, *whq32 = nullptr;
    cudaGetSymbolAddress(&gen_ptr, g_gen);
    cudaGetSymbolAddress(&whq32, g_Whq32);

    cudaMemsetAsync(gen_ptr, 0, sizeof(unsigned), 0);

    // Round W_hq to tf32 (rne): 4 float4 per thread, MLP=4
    {
        int n4 = HID * VOCAB / 4;
        int blocks = (n4 + 1023) / 1024;
        k_round4<<<blocks, 256>>>(Whq, (float*)whq32, n4);
    }
    k_embed_mma<<<dim3(HID / 128, M_TOTAL / 128), 256, K1_SMEM>>>(X, We, Wxh, bh);
    k_rnn_tc<<<NCTA2, 512, RNN2_SMEM>>>(Whh);
    k_out_gemm2<<<dim3(M_TOTAL / BM3, VOCAB / BN3), 256, K3_SMEM>>>(bq, out);
}